// round 17
// baseline (speedup 1.0000x reference)
#include <cuda_runtime.h>
#include <cstdint>

#define LL 4096
#define CC 32
#define LT 8            // l per CTA; warp w owns l = l0 + w
#define THREADS 256     // 8 warps
#define BCH 16          // b rows per chunk (one m16 tile)
#define NCH 4           // chunks per CTA (64 b)
#define BSPLIT 2        // b halves across CTAs

#define XPLANE 512      // u32 per l-plane (16B-aligned); s-shift lives in slot index
#define XBUF   (LT * XPLANE)     // 4096 u32 per x buffer
#define OPITCH 20                // banks 8q+p at compute store: conflict-free
#define OPLANE 644               // gather: per-instr uniform offset, conflict-free
#define OBUF   (LT * OPLANE)     // 5152 floats per o buffer
#define SMEM_BYTES ((2 * XBUF + 2 * OBUF + LT * CC) * 4)   // 75008 B

__device__ __forceinline__ uint32_t f2tf32(float f) {
    uint32_t r;
    asm("cvt.rna.tf32.f32 %0, %1;" : "=r"(r) : "f"(f));
    return r;
}

__device__ __forceinline__ void mma_tf32(
    float& d0, float& d1, float& d2, float& d3,
    uint32_t a0, uint32_t a1, uint32_t a2, uint32_t a3,
    uint32_t b0, uint32_t b1,
    float c0, float c1, float c2, float c3) {
    asm("mma.sync.aligned.m16n8k8.row.col.f32.tf32.tf32.f32 "
        "{%0,%1,%2,%3}, {%4,%5,%6,%7}, {%8,%9}, {%10,%11,%12,%13};"
        : "=f"(d0), "=f"(d1), "=f"(d2), "=f"(d3)
        : "r"(a0), "r"(a1), "r"(a2), "r"(a3), "r"(b0), "r"(b1),
          "f"(c0), "f"(c1), "f"(c2), "f"(c3));
}

__global__ void __launch_bounds__(THREADS, 3)
dyna_dec_kernel(const float* __restrict__ x, const float* __restrict__ weight,
                const float* __restrict__ bias, float* __restrict__ out) {
    extern __shared__ __align__(16) char smem[];
    uint32_t* x_s    = (uint32_t*)smem;                       // [2][XBUF]
    float*    o_s    = (float*)(smem + 2 * XBUF * 4);         // [2][OBUF]
    float*    bias_s = (float*)(smem + (2 * XBUF + 2 * OBUF) * 4);

    const int tid  = threadIdx.x;
    const int w    = tid >> 5;       // warp = local l
    const int lane = tid & 31;
    const int q    = lane & 3;       // mma k-in-tile
    const int p    = lane >> 2;      // mma row/col group
    const int b0   = blockIdx.x * (BCH * NCH);   // b-split fastest: weight L2 reuse
    const int l0   = blockIdx.y * LT;
    const int lg   = l0 + w;

    // ---------- prologue: issue chunk-0 prefetch FIRST ----------
    float4 pf[4];
    #pragma unroll
    for (int it = 0; it < 4; it++) {
        int i = it * THREADS + tid;
        int s = i & 1, r = i >> 1;
        pf[it] = *(const float4*)(x + ((size_t)((b0 + (r >> 5)) * CC + (r & 31))) * LL + l0 + 4 * s);
    }
    if (tid < 64)
        *(float4*)(bias_s + tid * 4) = *(const float4*)(bias + (size_t)l0 * CC + tid * 4);

    // ---- B fragments (32 regs) for this warp's l ----
    uint32_t bf[4][4][2];
    {
        const float* wp = weight + (size_t)lg * CC * CC;
        #pragma unroll
        for (int nt = 0; nt < 4; nt++)
            #pragma unroll
            for (int kt = 0; kt < 4; kt++) {
                bf[kt][nt][0] = f2tf32(__ldg(wp + (8 * kt + q) * CC + 8 * nt + p));
                bf[kt][nt][1] = f2tf32(__ldg(wp + (8 * kt + q + 4) * CC + 8 * nt + p));
            }
    }

    for (int ch = 0; ch < NCH; ch++) {
        uint32_t* xb = x_s + (ch & 1) * XBUF;

        // ---- stage prefetched chunk into x_s[parity] (conflict-free STS) ----
        #pragma unroll
        for (int it = 0; it < 4; it++) {
            int i = it * THREADS + tid;
            int s = i & 1, r = i >> 1;
            int bl = r >> 5, c = r & 31;
            // perm(c)+row rot 4(bl&7)+seg rot 4s: banks disjoint (R16-verified)
            int e = ((((c & 3) << 3) | ((c >> 3) << 1) | ((c >> 2) & 1))
                     + 4 * (bl & 7) + 4 * s) & 31;
            uint32_t* dst = xb + bl * CC + e;
            float4 v = pf[it];
            dst[(4 * s + 0) * XPLANE] = f2tf32(v.x);
            dst[(4 * s + 1) * XPLANE] = f2tf32(v.y);
            dst[(4 * s + 2) * XPLANE] = f2tf32(v.z);
            dst[(4 * s + 3) * XPLANE] = f2tf32(v.w);
        }
        // ---- prefetch next chunk ----
        if (ch + 1 < NCH) {
            int cbn = b0 + (ch + 1) * BCH;
            #pragma unroll
            for (int it = 0; it < 4; it++) {
                int i = it * THREADS + tid;
                int s = i & 1, r = i >> 1;
                pf[it] = *(const float4*)(x + ((size_t)((cbn + (r >> 5)) * CC + (r & 31))) * LL + l0 + 4 * s);
            }
        }
        __syncthreads();   // the ONLY barrier per chunk (protects x_s + o_s parities)

        // ---- compute(ch) -> o_s[parity]  (mma chain) ----
        {
            const uint32_t* xp = xb + w * XPLANE;
            const int rot = 4 * p + 4 * (w >> 2);
            const int o1 = (8 * q + rot) & 31;
            const int o2 = (8 * q + 4 + rot) & 31;
            uint4 v00 = *(const uint4*)(xp + p * CC + o1);
            uint4 v01 = *(const uint4*)(xp + p * CC + o2);
            uint4 v10 = *(const uint4*)(xp + (p + 8) * CC + o1);
            uint4 v11 = *(const uint4*)(xp + (p + 8) * CC + o2);

            float* op = o_s + (ch & 1) * OBUF + w * OPLANE;
            const float* bp = bias_s + w * CC;
            #pragma unroll
            for (int nt = 0; nt < 4; nt++) {
                float2 bv = *(const float2*)(bp + 8 * nt + 2 * q);
                float a0 = bv.x, a1 = bv.y, a2 = bv.x, a3 = bv.y;
                mma_tf32(a0, a1, a2, a3, v00.x, v10.x, v00.y, v10.y,
                         bf[0][nt][0], bf[0][nt][1], a0, a1, a2, a3);
                mma_tf32(a0, a1, a2, a3, v00.z, v10.z, v00.w, v10.w,
                         bf[1][nt][0], bf[1][nt][1], a0, a1, a2, a3);
                mma_tf32(a0, a1, a2, a3, v01.x, v11.x, v01.y, v11.y,
                         bf[2][nt][0], bf[2][nt][1], a0, a1, a2, a3);
                mma_tf32(a0, a1, a2, a3, v01.z, v11.z, v01.w, v11.w,
                         bf[3][nt][0], bf[3][nt][1], a0, a1, a2, a3);
                int d = 8 * nt + 2 * q;          // store banks 8q+p: conflict-free
                op[d * OPITCH + p]           = a0;
                op[(d + 1) * OPITCH + p]     = a1;
                op[d * OPITCH + p + 8]       = a2;
                op[(d + 1) * OPITCH + p + 8] = a3;
            }
        }

        // ---- out-pass(ch-1) from o_s[parity^1] — overlaps the mma chain ----
        if (ch > 0) {
            const float* ob = o_s + ((ch & 1) ^ 1) * OBUF;
            const int cb = b0 + (ch - 1) * BCH;
            const int bl = lane & 15, s2 = lane >> 4;
            #pragma unroll
            for (int it = 0; it < 4; it++) {
                int d = it * 8 + w;
                const float* src = ob + (4 * s2) * OPLANE + d * OPITCH + bl;
                float4 v;
                v.x = src[0 * OPLANE];
                v.y = src[1 * OPLANE];
                v.z = src[2 * OPLANE];
                v.w = src[3 * OPLANE];
                *(float4*)(out + ((size_t)((cb + bl) * CC + d)) * LL + l0 + 4 * s2) = v;
            }
        }
    }

    // ---- epilogue: flush out-pass for the last chunk ----
    __syncthreads();
    {
        const float* ob = o_s + ((NCH - 1) & 1) * OBUF;
        const int cb = b0 + (NCH - 1) * BCH;
        const int bl = lane & 15, s2 = lane >> 4;
        #pragma unroll
        for (int it = 0; it < 4; it++) {
            int d = it * 8 + w;
            const float* src = ob + (4 * s2) * OPLANE + d * OPITCH + bl;
            float4 v;
            v.x = src[0 * OPLANE];
            v.y = src[1 * OPLANE];
            v.z = src[2 * OPLANE];
            v.w = src[3 * OPLANE];
            *(float4*)(out + ((size_t)((cb + bl) * CC + d)) * LL + l0 + 4 * s2) = v;
        }
    }
}

extern "C" void kernel_launch(void* const* d_in, const int* in_sizes, int n_in,
                              void* d_out, int out_size) {
    const float* x      = (const float*)d_in[0];
    // d_in[1] = px, unused by the reference
    const float* weight = (const float*)d_in[2];
    const float* bias   = (const float*)d_in[3];
    float* out          = (float*)d_out;

    cudaFuncSetAttribute(dyna_dec_kernel, cudaFuncAttributeMaxDynamicSharedMemorySize,
                         SMEM_BYTES);
    dim3 grid(BSPLIT, LL / LT);   // (2, 512): weight-sharing siblings adjacent
    dim3 block(THREADS);
    dyna_dec_kernel<<<grid, block, SMEM_BYTES>>>(x, weight, bias, out);
}